// round 14
// baseline (speedup 1.0000x reference)
#include <cuda_runtime.h>
#include <cstdint>

#define NN 50000
#define EE 800000
#define HB 256          // histogram blocks inside prep kernel
#define NB 782          // node blocks per type: ceil(50000/64)
#define EGB 6250        // phase-1 edge blocks per relation (128 edges/block)

typedef unsigned long long u64;

// ---------------- scratch (device globals; no allocation allowed) ----------------
__device__ __align__(16) float g_sq_a[NN * 2];
__device__ __align__(16) float g_sk_a[NN * 2];
__device__ __align__(16) float g_sq_b[NN * 2];
__device__ __align__(16) float g_sk_b[NN * 2];
__device__ __align__(16) float g_v1[NN * 64];     // v_a + rel1 (natural col order)
__device__ __align__(16) float g_v2[NN * 64];     // v_b + rel2
__device__ __align__(16) float g_m1[NN * 64];     // normalized Σex*v, dst = b
__device__ __align__(16) float g_m2[NN * 64];     // dst = a
__device__ __align__(16) float g_t1[NN * 32];     // normalized Σex*ea per head
__device__ __align__(16) float g_t2[NN * 32];
__device__ __align__(16) float g_ex1[EE * 2];     // per-edge softmax numerators
__device__ __align__(16) float g_ex2[EE * 2];
__device__ int g_cnt1[NN],     g_cnt2[NN];
__device__ int g_off1[NN + 1], g_off2[NN + 1];
__device__ int g_cur1[NN],     g_cur2[NN];
__device__ __align__(16) u64 g_pair1[EE];         // (e << 32) | row[e], grouped by col
__device__ __align__(16) u64 g_pair2[EE];

// ---------------- helpers ----------------
__device__ __forceinline__ float tanh_fast(float x) {
    float y;
    asm("tanh.approx.f32 %0, %1;" : "=f"(y) : "f"(x));
    return y;
}
__device__ __forceinline__ u64 pack2(float lo, float hi) {
    u64 r;
    asm("mov.b64 %0, {%1, %2};" : "=l"(r) : "f"(lo), "f"(hi));
    return r;
}
__device__ __forceinline__ void unpack2(u64 v, float& lo, float& hi) {
    asm("mov.b64 {%0, %1}, %2;" : "=f"(lo), "=f"(hi) : "l"(v));
}
__device__ __forceinline__ u64 fma2(u64 a, u64 b, u64 c) {
    u64 d;
    asm("fma.rn.f32x2 %0, %1, %2, %3;" : "=l"(d) : "l"(a), "l"(b), "l"(c));
    return d;
}

// ---------------- zero counters ----------------
__global__ void zero_cnt_kernel() {
    int i = blockIdx.x * 256 + threadIdx.x;
    if (i < NN) { g_cnt1[i] = 0; g_cnt2[i] = 0; }
}

// ---------------- prep: histogram + fused-QKV node precompute ----------------
// blocks [0,HB): histogram over col1/col2. [HB, HB+2NB): QKV (64 nodes/block,
// 256 threads, 4-node x 4-col f32x2 tile, 3 blocks/SM).
#define PREP_SMEM ((4160 + 3 * 4096 + 192) * 4)

__global__ void __launch_bounds__(256, 3) prep_kernel(
    const float* __restrict__ x_a, const float* __restrict__ Wq_a,
    const float* __restrict__ Wk_a, const float* __restrict__ Wv_a,
    const float* __restrict__ x_b, const float* __restrict__ Wq_b,
    const float* __restrict__ Wk_b, const float* __restrict__ Wv_b,
    const float* __restrict__ emb_a, const float* __restrict__ emb_b,
    const float* __restrict__ rel1, const float* __restrict__ rel2,
    const float* __restrict__ a_attn,
    const int* __restrict__ col1, const int* __restrict__ col2)
{
    int b = blockIdx.x;
    int tid = threadIdx.x;

    if (b < HB) {
        const int S = HB * 256;
        for (int k = b * 256 + tid; k < 2 * EE; k += S) {
            if (k < EE) atomicAdd(&g_cnt1[__ldg(col1 + k)], 1);
            else        atomicAdd(&g_cnt2[__ldg(col2 + k - EE)], 1);
        }
        return;
    }
    b -= HB;
    int type = (b >= NB) ? 1 : 0;
    if (type) b -= NB;

    const float* x   = type ? x_b  : x_a;
    const float* Wqg = type ? Wq_b : Wq_a;
    const float* Wkg = type ? Wk_b : Wk_a;
    const float* Wvg = type ? Wv_b : Wv_a;
    const float* emb = type ? emb_b : emb_a;
    const float* rel = type ? rel2 : rel1;
    float* sq   = type ? g_sq_b : g_sq_a;
    float* sk   = type ? g_sk_b : g_sk_a;
    float* vout = type ? g_v2   : g_v1;

    extern __shared__ float sm[];
    float* xs   = sm;              // 64 x 65
    float* Wq   = sm + 4160;
    float* Wk   = Wq + 4096;
    float* Wv   = Wk + 4096;
    float* embS = Wv + 4096;
    float* relS = embS + 64;
    float* aS   = relS + 64;

    int nb = b * 64;

    for (int i = tid; i < 4096; i += 256) {
        int rr = i >> 6, cc = i & 63;
        int n2 = nb + rr;
        xs[rr * 65 + cc] = (n2 < NN) ? __ldg(x + n2 * 64 + cc) : 0.f;
        Wq[i] = __ldg(Wqg + i);
        Wk[i] = __ldg(Wkg + i);
        Wv[i] = __ldg(Wvg + i);
    }
    if (tid < 64) { embS[tid] = emb[tid]; relS[tid] = rel[tid]; aS[tid] = a_attn[tid]; }
    __syncthreads();

    int g = tid >> 4, cg = tid & 15, c0 = cg * 4;   // g: node quad 0..15
    int n0 = nb + g * 4;

    const ulonglong2* WqV = (const ulonglong2*)Wq;
    const ulonglong2* WkV = (const ulonglong2*)Wk;
    const ulonglong2* WvV = (const ulonglong2*)Wv;

    u64 Aq[8], Ak[8], Av[8];
#pragma unroll
    for (int i = 0; i < 8; i++) { Aq[i] = 0; Ak[i] = 0; Av[i] = 0; }

#pragma unroll 4
    for (int j = 0; j < 64; j++) {
        ulonglong2 wq = WqV[j * 16 + cg];
        ulonglong2 wk = WkV[j * 16 + cg];
        ulonglong2 wv = WvV[j * 16 + cg];
#pragma unroll
        for (int r = 0; r < 4; r++) {
            float xv = xs[(g * 4 + r) * 65 + j];
            u64 x2 = pack2(xv, xv);
            Aq[r * 2 + 0] = fma2(x2, wq.x, Aq[r * 2 + 0]);
            Aq[r * 2 + 1] = fma2(x2, wq.y, Aq[r * 2 + 1]);
            Ak[r * 2 + 0] = fma2(x2, wk.x, Ak[r * 2 + 0]);
            Ak[r * 2 + 1] = fma2(x2, wk.y, Ak[r * 2 + 1]);
            Av[r * 2 + 0] = fma2(x2, wv.x, Av[r * 2 + 0]);
            Av[r * 2 + 1] = fma2(x2, wv.y, Av[r * 2 + 1]);
        }
    }

    float aq[16], ak[16], av[16];
#pragma unroll
    for (int r = 0; r < 4; r++) {
        unpack2(Aq[r * 2 + 0], aq[r * 4 + 0], aq[r * 4 + 1]);
        unpack2(Aq[r * 2 + 1], aq[r * 4 + 2], aq[r * 4 + 3]);
        unpack2(Ak[r * 2 + 0], ak[r * 4 + 0], ak[r * 4 + 1]);
        unpack2(Ak[r * 2 + 1], ak[r * 4 + 2], ak[r * 4 + 3]);
        unpack2(Av[r * 2 + 0], av[r * 4 + 0], av[r * 4 + 1]);
        unpack2(Av[r * 2 + 1], av[r * 4 + 2], av[r * 4 + 3]);
    }

    float pq[4], pk[4];
#pragma unroll
    for (int r = 0; r < 4; r++) {
        float sQ = 0.f, sK = 0.f;
#pragma unroll
        for (int k = 0; k < 4; k++) {
            int c = c0 + k;
            sQ += tanh_fast(aq[r * 4 + k] + embS[c]) * aS[c & 31];
            sK += tanh_fast(ak[r * 4 + k] + embS[c]) * aS[32 + (c & 31)];
        }
        pq[r] = sQ; pk[r] = sK;
    }
#pragma unroll
    for (int m = 1; m < 8; m <<= 1) {
#pragma unroll
        for (int r = 0; r < 4; r++) {
            pq[r] += __shfl_xor_sync(0xffffffffu, pq[r], m);
            pk[r] += __shfl_xor_sync(0xffffffffu, pk[r], m);
        }
    }
    if ((cg & 7) == 0) {
        int h = cg >> 3;
#pragma unroll
        for (int r = 0; r < 4; r++) {
            int n = n0 + r;
            if (n < NN) { sq[n * 2 + h] = pq[r]; sk[n * 2 + h] = pk[r]; }
        }
    }

#pragma unroll
    for (int r = 0; r < 4; r++) {
        int n = n0 + r;
        if (n < NN) {
            *(float4*)(vout + (size_t)n * 64 + c0) =
                make_float4(av[r*4+0] + relS[c0+0], av[r*4+1] + relS[c0+1],
                            av[r*4+2] + relS[c0+2], av[r*4+3] + relS[c0+3]);
        }
    }
}

// ---------------- scan: exclusive prefix over counts -> offsets + cursors ----------------
__global__ void __launch_bounds__(1024) scan_kernel() {
    int rel = blockIdx.x;
    const int* cnt = rel ? g_cnt2 : g_cnt1;
    int* off = rel ? g_off2 : g_off1;
    int* cur = rel ? g_cur2 : g_cur1;
    int t = threadIdx.x;
    const int C = (NN + 1023) / 1024;   // 49
    int s = t * C;
    int e = (s + C < NN) ? s + C : NN;

    int local = 0;
    for (int i = s; i < e; i++) local += cnt[i];

    __shared__ int wsum[32];
    int lane = t & 31, wid = t >> 5;
    int v = local;
#pragma unroll
    for (int m = 1; m < 32; m <<= 1) {
        int u = __shfl_up_sync(0xffffffffu, v, m);
        if (lane >= m) v += u;
    }
    if (lane == 31) wsum[wid] = v;
    __syncthreads();
    if (wid == 0) {
        int wv = wsum[lane];
#pragma unroll
        for (int m = 1; m < 32; m <<= 1) {
            int u = __shfl_up_sync(0xffffffffu, wv, m);
            if (lane >= m) wv += u;
        }
        wsum[lane] = wv;
    }
    __syncthreads();
    int run = v - local + ((wid > 0) ? wsum[wid - 1] : 0);
    for (int i = s; i < e; i++) { off[i] = run; cur[i] = run; run += cnt[i]; }
    if (t == 0) off[NN] = EE;
}

// ---------------- scatter: build (e, row) pairs grouped by dst ----------------
__global__ void __launch_bounds__(256) scatter_kernel(
    const int* __restrict__ row1, const int* __restrict__ col1,
    const int* __restrict__ row2, const int* __restrict__ col2)
{
    const int S = gridDim.x * 256;
    for (int k = blockIdx.x * 256 + threadIdx.x; k < 2 * EE; k += S) {
        if (k < EE) {
            int c = __ldg(col1 + k);
            int pos = atomicAdd(&g_cur1[c], 1);
            g_pair1[pos] = ((u64)(unsigned)k << 32) | (unsigned)__ldg(row1 + k);
        } else {
            int e2 = k - EE;
            int c = __ldg(col2 + e2);
            int pos = atomicAdd(&g_cur2[c], 1);
            g_pair2[pos] = ((u64)(unsigned)e2 << 32) | (unsigned)__ldg(row2 + e2);
        }
    }
}

// ---------------- phase 1: edge-parallel score -> ex (no big atomics) ----------------
// 8 threads/edge; f32x2 GEMV; coalesced float2 store of (ex0, ex1).
__global__ void __launch_bounds__(256) score_kernel(
    const float* __restrict__ ea1, const int* __restrict__ row1, const int* __restrict__ col1,
    const float* __restrict__ ea2, const int* __restrict__ row2, const int* __restrict__ col2,
    const float* __restrict__ We, const float* __restrict__ a_attn)
{
    int bb = blockIdx.x;
    int relid = (bb >= EGB) ? 1 : 0;
    if (relid) bb -= EGB;

    const float* ea  = relid ? ea2  : ea1;
    const int*   row = relid ? row2 : row1;
    const int*   col = relid ? col2 : col1;
    const float* sq  = relid ? g_sq_a : g_sq_b;   // destination-node q scalar
    const float* sk  = relid ? g_sk_b : g_sk_a;   // source-node k scalar
    float* exb = relid ? g_ex2 : g_ex1;

    __shared__ __align__(16) float WeS[1024];     // [16][64] natural
    __shared__ float a4S[32];
    int tid = threadIdx.x;
    for (int i = tid; i < 1024; i += 256) WeS[i] = We[i];
    if (tid < 32) a4S[tid] = a_attn[96 + tid];
    __syncthreads();

    int lane = tid & 7;
    int grp  = tid >> 3;
    const ulonglong2* WeV = (const ulonglong2*)WeS;   // row j = 16 ulonglong2

#pragma unroll 1
    for (int it = 0; it < 4; it++) {
        int e = (bb * 4 + it) * 32 + grp;
        int r = __ldg(row + e), c = __ldg(col + e);

        const float4* ea4p = (const float4*)ea + (size_t)e * 4;
        float4 A = __ldg(ea4p), B = __ldg(ea4p + 1), C = __ldg(ea4p + 2), D = __ldg(ea4p + 3);
        float ear[16] = {A.x, A.y, A.z, A.w, B.x, B.y, B.z, B.w,
                         C.x, C.y, C.z, C.w, D.x, D.y, D.z, D.w};

        u64 a01 = 0, a23 = 0, a45 = 0, a67 = 0;
#pragma unroll
        for (int j = 0; j < 16; j++) {
            u64 ev2 = pack2(ear[j], ear[j]);
            ulonglong2 w0 = WeV[j * 16 + lane];        // cols 4l..4l+3
            ulonglong2 w1 = WeV[j * 16 + 8 + lane];    // cols 32+4l..32+4l+3
            a01 = fma2(ev2, w0.x, a01);
            a23 = fma2(ev2, w0.y, a23);
            a45 = fma2(ev2, w1.x, a45);
            a67 = fma2(ev2, w1.y, a67);
        }
        float acc[8];
        unpack2(a01, acc[0], acc[1]); unpack2(a23, acc[2], acc[3]);
        unpack2(a45, acc[4], acc[5]); unpack2(a67, acc[6], acc[7]);

        float se0 = 0.f, se1 = 0.f;
#pragma unroll
        for (int t = 0; t < 4; t++) {
            float av = a4S[4 * lane + t];
            se0 += tanh_fast(acc[t])     * av;
            se1 += tanh_fast(acc[4 + t]) * av;
        }
#pragma unroll
        for (int m = 1; m < 8; m <<= 1) {
            se0 += __shfl_xor_sync(0xffffffffu, se0, m);
            se1 += __shfl_xor_sync(0xffffffffu, se1, m);
        }

        float2 sqv = __ldg((const float2*)sq + c);
        float2 skv = __ldg((const float2*)sk + r);
        float ex0 = __expf(sqv.x + skv.x + se0);
        float ex1 = __expf(sqv.y + skv.y + se1);

        if (lane == 0)
            *(float2*)(exb + (size_t)e * 2) = make_float2(ex0, ex1);
    }
}

// ---------------- phase 2: gather per destination node (warp-per-node) ----------------
// 4 edges/iter x 8 lanes; register accumulation of Σex*v (64f), Σex*ea (32f), Σex;
// normalize and plain-store. No atomics.
__global__ void __launch_bounds__(256) gather_kernel(
    const float* __restrict__ ea1, const float* __restrict__ ea2)
{
    int tid  = threadIdx.x;
    int w    = tid >> 5;
    int lane = tid & 31;
    int grp  = lane >> 3, l8 = lane & 7;

    int gd  = blockIdx.x * 8 + w;                 // 0 .. 2*NN-1
    int rel = (gd >= NN) ? 1 : 0;
    int c   = rel ? gd - NN : gd;

    const float* ea   = rel ? ea2    : ea1;
    const int*   off  = rel ? g_off2 : g_off1;
    const u64*   pair = rel ? g_pair2 : g_pair1;
    const float* exb  = rel ? g_ex2  : g_ex1;
    const float* vsrc = rel ? g_v2   : g_v1;
    float* mbuf = rel ? g_m2 : g_m1;
    float* tbuf = rel ? g_t2 : g_t1;

    int off0 = __ldg(off + c);
    int deg  = __ldg(off + c + 1) - off0;

    if (deg == 0) {
        if (grp == 0) {
            const float4 z = make_float4(0.f, 0.f, 0.f, 0.f);
            *(float4*)(mbuf + (size_t)c * 64 + 4 * l8) = z;
            *(float4*)(mbuf + (size_t)c * 64 + 32 + 4 * l8) = z;
            *(float4*)(tbuf + (size_t)c * 32 + 4 * l8) = z;
        }
        return;
    }

    float m0x=0,m0y=0,m0z=0,m0w=0, m1x=0,m1y=0,m1z=0,m1w=0;
    float t0=0,t1=0,t2=0,t3=0;
    float den0=0.f, den1=0.f;
    int q = l8 & 3, h = l8 >> 2;

#pragma unroll 1
    for (int base = 0; base < deg; base += 4) {
        int slot = base + grp;
        bool valid = slot < deg;
        int idx = off0 + (valid ? slot : 0);
        u64 pr = __ldg(pair + idx);
        int r = (int)(unsigned)(pr & 0xffffffffu);
        int e = (int)(unsigned)(pr >> 32);

        float2 ex = __ldg((const float2*)exb + e);
        if (!valid) { ex.x = 0.f; ex.y = 0.f; }

        const float4* vp = (const float4*)(vsrc + (size_t)r * 64);
        float4 v0 = __ldg(vp + l8);               // cols 4l8..4l8+3 (head 0)
        float4 v1 = __ldg(vp + 8 + l8);           // cols 32+4l8..   (head 1)
        m0x = fmaf(ex.x, v0.x, m0x); m0y = fmaf(ex.x, v0.y, m0y);
        m0z = fmaf(ex.x, v0.z, m0z); m0w = fmaf(ex.x, v0.w, m0w);
        m1x = fmaf(ex.y, v1.x, m1x); m1y = fmaf(ex.y, v1.y, m1y);
        m1z = fmaf(ex.y, v1.z, m1z); m1w = fmaf(ex.y, v1.w, m1w);

        float4 eaq = __ldg((const float4*)(ea + (size_t)e * 16) + q);
        float exh = h ? ex.y : ex.x;
        t0 = fmaf(exh, eaq.x, t0); t1 = fmaf(exh, eaq.y, t1);
        t2 = fmaf(exh, eaq.z, t2); t3 = fmaf(exh, eaq.w, t3);

        den0 += ex.x; den1 += ex.y;
    }

    // merge the 4 edge-slot groups (l8 preserved)
#pragma unroll
    for (int m = 8; m <= 16; m <<= 1) {
        m0x += __shfl_xor_sync(0xffffffffu, m0x, m);
        m0y += __shfl_xor_sync(0xffffffffu, m0y, m);
        m0z += __shfl_xor_sync(0xffffffffu, m0z, m);
        m0w += __shfl_xor_sync(0xffffffffu, m0w, m);
        m1x += __shfl_xor_sync(0xffffffffu, m1x, m);
        m1y += __shfl_xor_sync(0xffffffffu, m1y, m);
        m1z += __shfl_xor_sync(0xffffffffu, m1z, m);
        m1w += __shfl_xor_sync(0xffffffffu, m1w, m);
        t0  += __shfl_xor_sync(0xffffffffu, t0, m);
        t1  += __shfl_xor_sync(0xffffffffu, t1, m);
        t2  += __shfl_xor_sync(0xffffffffu, t2, m);
        t3  += __shfl_xor_sync(0xffffffffu, t3, m);
        den0 += __shfl_xor_sync(0xffffffffu, den0, m);
        den1 += __shfl_xor_sync(0xffffffffu, den1, m);
    }

    if (grp == 0) {
        float i0 = 1.0f / den0, i1 = 1.0f / den1;
        *(float4*)(mbuf + (size_t)c * 64 + 4 * l8) =
            make_float4(m0x * i0, m0y * i0, m0z * i0, m0w * i0);
        *(float4*)(mbuf + (size_t)c * 64 + 32 + 4 * l8) =
            make_float4(m1x * i1, m1y * i1, m1z * i1, m1w * i1);
        float ih = h ? i1 : i0;
        *(float4*)(tbuf + (size_t)c * 32 + 4 * l8) =
            make_float4(t0 * ih, t1 * ih, t2 * ih, t3 * ih);
    }
}

// ---------------- final: out = (m + t@We)@Wo + bo + x@Wr  (both types via grid.y) ----------------
__global__ void __launch_bounds__(256) final_kernel(
    const float* __restrict__ We,
    const float* __restrict__ Wo_a, const float* __restrict__ bo_a,
    const float* __restrict__ x_a,  const float* __restrict__ Wr_a,
    const float* __restrict__ Wo_b, const float* __restrict__ bo_b,
    const float* __restrict__ x_b,  const float* __restrict__ Wr_b,
    float* __restrict__ out)
{
    int type = blockIdx.y;   // 0 = a, 1 = b
    const float* Wo = type ? Wo_b : Wo_a;
    const float* bo = type ? bo_b : bo_a;
    const float* x  = type ? x_b  : x_a;
    const float* Wr = type ? Wr_b : Wr_a;
    const float* mb = type ? g_m1 : g_m2;   // a's messages come from relation 2
    const float* tb = type ? g_t1 : g_t2;
    float* outp = out + (size_t)type * NN * 32;

    __shared__ float afs[32][65];
    __shared__ float xs[32][65];
    __shared__ __align__(16) float WoS[64][32];
    __shared__ __align__(16) float WrS[64][32];
    __shared__ float WeS[16][64];
    __shared__ float tS[32][33];
    __shared__ float boS[32];

    int tid = threadIdx.x;
    int nb  = blockIdx.x * 32;

    if (tid < 32) boS[tid] = bo[tid];

    for (int i = tid; i < 2048; i += 256) {
        int s = i >> 5, o = i & 31;
        WoS[s][o] = Wo[s * 32 + o];
        WrS[s][o] = Wr[s * 32 + o];
        int n2 = nb + (i >> 6), c2 = i & 63;
        afs[i >> 6][c2] = (n2 < NN) ? mb[(size_t)n2 * 64 + c2] : 0.f;
        xs[i >> 6][c2]  = (n2 < NN) ? x[(size_t)n2 * 64 + c2] : 0.f;
    }
    for (int i = tid; i < 1024; i += 256) {
        WeS[i >> 6][i & 63] = We[i];
        int n2 = nb + (i >> 5);
        tS[i >> 5][i & 31] = (n2 < NN) ? tb[(size_t)n2 * 32 + (i & 31)] : 0.f;
    }
    __syncthreads();

    int nl = tid >> 3, p = tid & 7;
    int n = nb + nl;

    // phase A: af[cc] = m'[cc] + t'@We   (t' already normalized)
    float af[8];
#pragma unroll
    for (int i = 0; i < 8; i++) {
        int cc = p * 8 + i;
        int h = cc >> 5;
        float tw = afs[nl][cc];
#pragma unroll
        for (int j = 0; j < 16; j++)
            tw = fmaf(tS[nl][h * 16 + j], WeS[j][cc], tw);
        af[i] = tw;
    }
    __syncthreads();
#pragma unroll
    for (int i = 0; i < 8; i++) afs[nl][p * 8 + i] = af[i];
    __syncthreads();

    // phase B: out = af @ Wo + bo + x @ Wr  (f32x2)
    u64 o01 = pack2(boS[p * 4 + 0], boS[p * 4 + 1]);
    u64 o23 = pack2(boS[p * 4 + 2], boS[p * 4 + 3]);
#pragma unroll 8
    for (int k = 0; k < 64; k++) {
        float a  = afs[nl][k];
        float xv = xs[nl][k];
        u64 a2 = pack2(a, a);
        u64 x2 = pack2(xv, xv);
        ulonglong2 wo = *(const ulonglong2*)&WoS[k][p * 4];
        ulonglong2 wr = *(const ulonglong2*)&WrS[k][p * 4];
        o01 = fma2(a2, wo.x, o01); o23 = fma2(a2, wo.y, o23);
        o01 = fma2(x2, wr.x, o01); o23 = fma2(x2, wr.y, o23);
    }
    if (n < NN) {
        float o[4];
        unpack2(o01, o[0], o[1]); unpack2(o23, o[2], o[3]);
        float4* op = (float4*)(outp + (size_t)n * 32 + p * 4);
        op[0] = make_float4(o[0], o[1], o[2], o[3]);
    }
}

// ---------------- launch ----------------
extern "C" void kernel_launch(void* const* d_in, const int* in_sizes, int n_in,
                              void* d_out, int out_size)
{
    const float* x_a    = (const float*)d_in[0];
    const float* x_b    = (const float*)d_in[1];
    const float* ea1    = (const float*)d_in[2];
    const float* ea2    = (const float*)d_in[3];
    const float* Wq_a   = (const float*)d_in[4];
    const float* Wk_a   = (const float*)d_in[5];
    const float* Wv_a   = (const float*)d_in[6];
    const float* Wq_b   = (const float*)d_in[7];
    const float* Wk_b   = (const float*)d_in[8];
    const float* Wv_b   = (const float*)d_in[9];
    const float* emb_a  = (const float*)d_in[10];
    const float* emb_b  = (const float*)d_in[11];
    const float* rel1   = (const float*)d_in[12];
    const float* rel2   = (const float*)d_in[13];
    const float* We     = (const float*)d_in[14];
    const float* a_attn = (const float*)d_in[15];
    const float* Wo_a   = (const float*)d_in[16];
    const float* bo_a   = (const float*)d_in[17];
    const float* Wo_b   = (const float*)d_in[18];
    const float* bo_b   = (const float*)d_in[19];
    const float* Wr_a   = (const float*)d_in[20];
    const float* Wr_b   = (const float*)d_in[21];
    const int*   row1   = (const int*)d_in[22];
    const int*   col1   = (const int*)d_in[23];
    const int*   row2   = (const int*)d_in[24];
    const int*   col2   = (const int*)d_in[25];
    float* out = (float*)d_out;

    cudaFuncSetAttribute(prep_kernel, cudaFuncAttributeMaxDynamicSharedMemorySize, PREP_SMEM);

    zero_cnt_kernel<<<(NN + 255) / 256, 256>>>();

    prep_kernel<<<HB + 2 * NB, 256, PREP_SMEM>>>(x_a, Wq_a, Wk_a, Wv_a,
                                                 x_b, Wq_b, Wk_b, Wv_b,
                                                 emb_a, emb_b, rel1, rel2, a_attn,
                                                 col1, col2);

    scan_kernel<<<2, 1024>>>();

    scatter_kernel<<<2048, 256>>>(row1, col1, row2, col2);

    score_kernel<<<2 * EGB, 256>>>(ea1, row1, col1, ea2, row2, col2, We, a_attn);

    gather_kernel<<<2 * NN / 8, 256>>>(ea1, ea2);

    dim3 fg((NN + 31) / 32, 2);
    final_kernel<<<fg, 256>>>(We, Wo_a, bo_a, x_a, Wr_a,
                              Wo_b, bo_b, x_b, Wr_b, out);
}